// round 9
// baseline (speedup 1.0000x reference)
#include <cuda_runtime.h>
#include <cuda_fp16.h>
#include <cstdint>
#include <math.h>

#define M_DIM 16384
#define K_DIM 4096
#define N_DIM 4096

// fp16 copies of inputs + lse partials (static device scratch)
static __device__ __half g_xh[(size_t)M_DIM * K_DIM];
static __device__ __half g_wh[(size_t)N_DIM * K_DIM];
static __device__ float2 g_part[(size_t)M_DIM * 8];   // [row][nslice] (max,sum)

// ---------------- tile / smem geometry ----------------
constexpr int BM = 128;            // M tile per CTA
constexpr int BN = 256;            // N chunk per fold
constexpr int NSLICE = 8;          // N split across CTAs
constexpr int NS_COLS = N_DIM / NSLICE;      // 512
constexpr int NCHUNK_CTA = NS_COLS / BN;     // 2
constexpr int BK = 64;             // K halves per stage (128 B/row, SW128)
constexpr int NSTAGE = 4;
constexpr int KSTG = K_DIM / BK;             // 64
constexpr int TOTSTG = NCHUNK_CTA * KSTG;    // 128 stages per CTA

constexpr uint32_t A_STG = BM * 128;         // 16 KB
constexpr uint32_t B_STG = BN * 128;         // 32 KB
constexpr uint32_t STG   = A_STG + B_STG;    // 48 KB
constexpr uint32_t SMEM_BYTES = NSTAGE * STG + 1024;   // 197632

__device__ __forceinline__ uint32_t smem_u32(const void* p) {
    uint32_t a;
    asm("{ .reg .u64 t; cvta.to.shared.u64 t, %1; cvt.u32.u64 %0, t; }"
        : "=r"(a) : "l"(p));
    return a;
}
__device__ __forceinline__ uint32_t swz(uint32_t off) {   // SW128, 16B granule
    return off ^ ((off >> 3) & 0x70);
}
__device__ __forceinline__ void cp_async16(uint32_t dst, const void* src) {
    asm volatile("cp.async.cg.shared.global [%0], [%1], 16;"
                 :: "r"(dst), "l"(__cvta_generic_to_global(src)) : "memory");
}
#define CP_COMMIT() asm volatile("cp.async.commit_group;" ::: "memory")
#define CP_WAIT(n)  asm volatile("cp.async.wait_group %0;" :: "n"(n) : "memory")

__device__ __forceinline__ void ldsm4(uint32_t* r, uint32_t addr) {
    asm volatile("ldmatrix.sync.aligned.m8n8.x4.shared.b16 {%0,%1,%2,%3}, [%4];"
                 : "=r"(r[0]), "=r"(r[1]), "=r"(r[2]), "=r"(r[3]) : "r"(addr));
}
// fp16-accumulate MMA: D/C are 2 b32 regs (4 halves)
__device__ __forceinline__ void mma16816_h(uint32_t* c, const uint32_t* a, const uint32_t* b) {
    asm volatile(
        "mma.sync.aligned.m16n8k16.row.col.f16.f16.f16.f16 "
        "{%0,%1}, {%2,%3,%4,%5}, {%6,%7}, {%0,%1};"
        : "+r"(c[0]), "+r"(c[1])
        : "r"(a[0]), "r"(a[1]), "r"(a[2]), "r"(a[3]), "r"(b[0]), "r"(b[1]));
}

// ---------------- fp32 -> fp16 conversion ----------------
__global__ void __launch_bounds__(256) cvt_x_kernel(const float4* __restrict__ src, int n4) {
    int i = blockIdx.x * 256 + threadIdx.x;
    if (i >= n4) return;
    float4 v = src[i];
    __half2* d = reinterpret_cast<__half2*>(g_xh);
    d[2 * i]     = __floats2half2_rn(v.x, v.y);
    d[2 * i + 1] = __floats2half2_rn(v.z, v.w);
}
__global__ void __launch_bounds__(256) cvt_w_kernel(const float4* __restrict__ src, int n4) {
    int i = blockIdx.x * 256 + threadIdx.x;
    if (i >= n4) return;
    float4 v = src[i];
    __half2* d = reinterpret_cast<__half2*>(g_wh);
    d[2 * i]     = __floats2half2_rn(v.x, v.y);
    d[2 * i + 1] = __floats2half2_rn(v.z, v.w);
}

// ---------------- GEMM + partial logsumexp (per N-slice) ----------------
__global__ void __launch_bounds__(512, 1)
gemm_lse_part_kernel(const float* __restrict__ bias) {
    extern __shared__ char smem_raw[];
    const uint32_t sb0 = smem_u32(smem_raw);
    const uint32_t sb  = (sb0 + 1023u) & ~1023u;   // 1024-align
    char* sptr = smem_raw + (sb - sb0);

    const int tid  = threadIdx.x;
    const int wid  = tid >> 5;            // 0..15
    const int lane = tid & 31;
    const int mt   = blockIdx.x >> 3;     // m-tile (8 consecutive CTAs share A)
    const int ns   = blockIdx.x & 7;      // n-slice
    const int m0   = mt * BM;
    const int n0   = ns * NS_COLS;

    const int warpM = (wid >> 3) * 64;    // 0 or 64
    const int warpN = (wid & 7) * 32;     // 0..224 within BN

    // per-lane ldmatrix byte offsets (pre-swizzle)
    const int matid = lane >> 3, rin = lane & 7;
    int aRow[4], bRow[2];
    #pragma unroll
    for (int mi = 0; mi < 4; mi++)
        aRow[mi] = (warpM + mi * 16 + (matid & 1) * 8 + rin) * 128 + (matid >> 1) * 16;
    #pragma unroll
    for (int p = 0; p < 2; p++)
        bRow[p] = (warpN + p * 16 + (matid >> 1) * 8 + rin) * 128 + (matid & 1) * 16;

    // ---- producer precompute: j<2 -> A (1024 copies), j>=2 -> B (2048) ----
    const char* srcBase[6];
    uint32_t   preOff[6];
    #pragma unroll
    for (int j = 0; j < 6; j++) {
        const int c    = tid + 512 * j;           // 0..3071
        const bool isA = (j < 2);                 // compile-time per j
        const int rc   = isA ? c : c - 1024;
        const int row  = rc >> 3;
        const int c16  = rc & 7;
        srcBase[j] = isA
            ? (const char*)(g_xh + ((size_t)(m0 + row) * K_DIM + c16 * 8))
            : (const char*)(g_wh + ((size_t)(n0 + row) * K_DIM + c16 * 8));
        preOff[j] = (isA ? 0u : A_STG) + swz((uint32_t)(row * 128 + c16 * 16));
    }

    auto issue_stage = [&](int gs) {
        if (gs < TOTSTG) {
            const int slot  = gs & (NSTAGE - 1);
            const int chunk = gs >> 6;            // 0..1 (KSTG=64)
            const int ks    = gs & 63;
            const uint32_t offA = (uint32_t)ks << 7;                       // ks*128 B
            const uint32_t offB = (uint32_t)chunk * (BN * K_DIM * 2) + offA;
            const uint32_t slotBase = sb + slot * STG;
            #pragma unroll
            for (int j = 0; j < 6; j++)
                cp_async16(slotBase + preOff[j], srcBase[j] + (j < 2 ? offA : offB));
        }
        CP_COMMIT();
    };

    // fp16 accumulators: 4 m-tiles x 4 n-tiles x 2 regs
    uint32_t hacc[4][4][2];
    #pragma unroll
    for (int mi = 0; mi < 4; mi++)
        #pragma unroll
        for (int ni = 0; ni < 4; ni++) { hacc[mi][ni][0] = 0u; hacc[mi][ni][1] = 0u; }

    float rm[8], rs[8];
    #pragma unroll
    for (int s = 0; s < 8; s++) { rm[s] = -1e30f; rs[s] = 0.f; }

    // prologue: issue 3 stages, wait until stages 0 AND 1 are resident
    issue_stage(0); issue_stage(1); issue_stage(2);
    CP_WAIT(1);
    __syncthreads();

    // double-buffered fragments; preload g0 of stage 0
    uint32_t af[2][4][4], bt[2][2][4];
    {
        const uint32_t aB = sb, bB = sb + A_STG;
        #pragma unroll
        for (int mi = 0; mi < 4; mi++) ldsm4(af[0][mi], aB + swz((uint32_t)aRow[mi]));
        #pragma unroll
        for (int p = 0; p < 2; p++)    ldsm4(bt[0][p], bB + swz((uint32_t)bRow[p]));
    }

    const int tg = lane & 3;

    for (int chunk = 0; chunk < NCHUNK_CTA; ++chunk) {
        #pragma unroll 1
        for (int ks = 0; ks < KSTG; ++ks) {
            const int gs = chunk * KSTG + ks;
            const uint32_t aB = sb + (gs & (NSTAGE - 1)) * STG;
            const uint32_t bB = aB + A_STG;
            const uint32_t aBn = sb + ((gs + 1) & (NSTAGE - 1)) * STG;  // next stage
            const uint32_t bBn = aBn + A_STG;

            #pragma unroll
            for (int g = 0; g < 4; g++) {
                const int cur = g & 1, nxt = cur ^ 1;
                if (g < 3) {
                    // prefetch fragments for g+1 of this stage
                    #pragma unroll
                    for (int mi = 0; mi < 4; mi++)
                        ldsm4(af[nxt][mi], aB + swz((uint32_t)(aRow[mi] + (g + 1) * 32)));
                    #pragma unroll
                    for (int p = 0; p < 2; p++)
                        ldsm4(bt[nxt][p], bB + swz((uint32_t)(bRow[p] + (g + 1) * 32)));
                }
                if (g == 2) {
                    // stage gs+1 resident; all warps past stage gs-1 -> its slot reusable
                    CP_WAIT(1);
                    __syncthreads();
                    issue_stage(gs + 3);
                }
                if (g == 3 && gs + 1 < TOTSTG) {
                    // preload g0 fragments of next stage (post-bar: data visible)
                    #pragma unroll
                    for (int mi = 0; mi < 4; mi++)
                        ldsm4(af[nxt][mi], aBn + swz((uint32_t)aRow[mi]));
                    #pragma unroll
                    for (int p = 0; p < 2; p++)
                        ldsm4(bt[nxt][p], bBn + swz((uint32_t)bRow[p]));
                }
                #pragma unroll
                for (int mi = 0; mi < 4; mi++) {
                    mma16816_h(hacc[mi][0], af[cur][mi], &bt[cur][0][0]);
                    mma16816_h(hacc[mi][1], af[cur][mi], &bt[cur][0][2]);
                    mma16816_h(hacc[mi][2], af[cur][mi], &bt[cur][1][0]);
                    mma16816_h(hacc[mi][3], af[cur][mi], &bt[cur][1][2]);
                }
            }
        }

        // fold chunk logits (fp16 acc) into running (max, sum); bias via L2
        float bv[4][2];
        #pragma unroll
        for (int ni = 0; ni < 4; ni++) {
            const int nc = n0 + chunk * BN + warpN + ni * 8 + tg * 2;
            bv[ni][0] = bias[nc];
            bv[ni][1] = bias[nc + 1];
        }
        #pragma unroll
        for (int mi = 0; mi < 4; mi++) {
            #pragma unroll
            for (int h = 0; h < 2; h++) {
                const int s = mi * 2 + h;
                float v[8], lm = rm[s];
                #pragma unroll
                for (int ni = 0; ni < 4; ni++) {
                    __half2 hv = *reinterpret_cast<__half2*>(&hacc[mi][ni][h]);
                    float2 f = __half22float2(hv);
                    v[ni * 2]     = f.x + bv[ni][0];
                    v[ni * 2 + 1] = f.y + bv[ni][1];
                    lm = fmaxf(lm, v[ni * 2]);
                    lm = fmaxf(lm, v[ni * 2 + 1]);
                    hacc[mi][ni][h] = 0u;
                }
                float e = 0.f;
                #pragma unroll
                for (int j = 0; j < 8; j++) e += __expf(v[j] - lm);
                rs[s] = rs[s] * __expf(rm[s] - lm) + e;
                rm[s] = lm;
            }
        }
    }

    // cross-thread reduction: quad shuffle, then across 8 N-warps via smem
    __syncthreads();
    float2* red = reinterpret_cast<float2*>(sptr);   // 128 rows x 8 warps
    #pragma unroll
    for (int s = 0; s < 8; s++) {
        float m = rm[s], sm = rs[s];
        #pragma unroll
        for (int d = 1; d <= 2; d <<= 1) {
            float om = __shfl_xor_sync(0xffffffffu, m, d);
            float os = __shfl_xor_sync(0xffffffffu, sm, d);
            float nm = fmaxf(m, om);
            sm = sm * __expf(m - nm) + os * __expf(om - nm);
            m = nm;
        }
        if (tg == 0) {
            const int mi = s >> 1, h = s & 1;
            const int row = warpM + mi * 16 + (lane >> 2) + h * 8;
            red[row * 8 + (wid & 7)] = make_float2(m, sm);
        }
    }
    __syncthreads();

    if (tid < BM) {
        float m = -1e30f, sm = 0.f;
        #pragma unroll
        for (int w = 0; w < 8; w++) {
            float2 p = red[tid * 8 + w];
            float nm = fmaxf(m, p.x);
            sm = sm * __expf(m - nm) + p.y * __expf(p.x - nm);
            m = nm;
        }
        g_part[(size_t)(m0 + tid) * 8 + ns] = make_float2(m, sm);
    }
}

// ---------------- combine partials + activations ----------------
__global__ void __launch_bounds__(256) combine_kernel(float* __restrict__ out) {
    const int i = blockIdx.x * 256 + threadIdx.x;
    if (i >= M_DIM) return;
    float m = -1e30f, sm = 0.f;
    #pragma unroll
    for (int ns = 0; ns < 8; ns++) {       // fixed order -> deterministic
        float2 p = g_part[(size_t)i * 8 + ns];
        float nm = fmaxf(m, p.x);
        sm = sm * __expf(m - nm) + p.y * __expf(p.x - nm);
        m = nm;
    }
    float v = m + logf(sm);
    v = v > 0.f ? v : 0.01f * v;           // LeakyReLU x2
    v = v > 0.f ? v : 0.01f * v;
    v = v * 0.5f * (1.0f + erff(v * 0.70710678118654752f));   // GELU x2
    v = v * 0.5f * (1.0f + erff(v * 0.70710678118654752f));
    out[i] = v;
}

extern "C" void kernel_launch(void* const* d_in, const int* in_sizes, int n_in,
                              void* d_out, int out_size) {
    const float* x = (const float*)d_in[0];
    const float* W = (const float*)d_in[1];
    const float* b = (const float*)d_in[2];
    float* out = (float*)d_out;

    cudaFuncSetAttribute(gemm_lse_part_kernel,
                         cudaFuncAttributeMaxDynamicSharedMemorySize, SMEM_BYTES);

    const int x4 = (M_DIM * K_DIM) / 4;
    const int w4 = (N_DIM * K_DIM) / 4;
    cvt_x_kernel<<<(x4 + 255) / 256, 256>>>((const float4*)x, x4);
    cvt_w_kernel<<<(w4 + 255) / 256, 256>>>((const float4*)W, w4);
    gemm_lse_part_kernel<<<(M_DIM / BM) * NSLICE, 512, SMEM_BYTES>>>(b);
    combine_kernel<<<(M_DIM + 255) / 256, 256>>>(out);
}

// round 10
// speedup vs baseline: 1.1077x; 1.1077x over previous
#include <cuda_runtime.h>
#include <cuda_fp16.h>
#include <cstdint>
#include <math.h>

#define M_DIM 16384
#define K_DIM 4096
#define N_DIM 4096

// fp16 copies of inputs + lse partials (static device scratch)
static __device__ __half g_xh[(size_t)M_DIM * K_DIM];
static __device__ __half g_wh[(size_t)N_DIM * K_DIM];
static __device__ float2 g_part[(size_t)M_DIM * 16];  // [row][nslice] (max,sum)

// ---------------- tile / smem geometry ----------------
constexpr int BM = 128;            // M tile per CTA
constexpr int BN = 256;            // N cols per CTA (single chunk)
constexpr int NSLICE = 16;         // N split across CTAs
constexpr int BK = 64;             // K halves per stage (128 B/row, SW128)
constexpr int NSTAGE = 2;
constexpr int TOTSTG = K_DIM / BK;           // 64 stages per CTA

constexpr uint32_t A_STG = BM * 128;         // 16 KB
constexpr uint32_t B_STG = BN * 128;         // 32 KB
constexpr uint32_t STG   = A_STG + B_STG;    // 48 KB
constexpr uint32_t SMEM_BYTES = NSTAGE * STG + 1024;   // 99328 -> 2 CTAs/SM

__device__ __forceinline__ uint32_t smem_u32(const void* p) {
    uint32_t a;
    asm("{ .reg .u64 t; cvta.to.shared.u64 t, %1; cvt.u32.u64 %0, t; }"
        : "=r"(a) : "l"(p));
    return a;
}
__device__ __forceinline__ uint32_t swz(uint32_t off) {   // SW128, 16B granule
    return off ^ ((off >> 3) & 0x70);
}
__device__ __forceinline__ void cp_async16(uint32_t dst, const void* src) {
    asm volatile("cp.async.cg.shared.global [%0], [%1], 16;"
                 :: "r"(dst), "l"(__cvta_generic_to_global(src)) : "memory");
}
#define CP_COMMIT() asm volatile("cp.async.commit_group;" ::: "memory")
#define CP_WAIT(n)  asm volatile("cp.async.wait_group %0;" :: "n"(n) : "memory")

__device__ __forceinline__ void ldsm4(uint32_t* r, uint32_t addr) {
    asm volatile("ldmatrix.sync.aligned.m8n8.x4.shared.b16 {%0,%1,%2,%3}, [%4];"
                 : "=r"(r[0]), "=r"(r[1]), "=r"(r[2]), "=r"(r[3]) : "r"(addr));
}
// fp16-accumulate MMA: D/C are 2 b32 regs (4 halves)
__device__ __forceinline__ void mma16816_h(uint32_t* c, const uint32_t* a, const uint32_t* b) {
    asm volatile(
        "mma.sync.aligned.m16n8k16.row.col.f16.f16.f16.f16 "
        "{%0,%1}, {%2,%3,%4,%5}, {%6,%7}, {%0,%1};"
        : "+r"(c[0]), "+r"(c[1])
        : "r"(a[0]), "r"(a[1]), "r"(a[2]), "r"(a[3]), "r"(b[0]), "r"(b[1]));
}

// ---------------- fp32 -> fp16 conversion ----------------
__global__ void __launch_bounds__(256) cvt_x_kernel(const float4* __restrict__ src, int n4) {
    int i = blockIdx.x * 256 + threadIdx.x;
    if (i >= n4) return;
    float4 v = src[i];
    __half2* d = reinterpret_cast<__half2*>(g_xh);
    d[2 * i]     = __floats2half2_rn(v.x, v.y);
    d[2 * i + 1] = __floats2half2_rn(v.z, v.w);
}
__global__ void __launch_bounds__(256) cvt_w_kernel(const float4* __restrict__ src, int n4) {
    int i = blockIdx.x * 256 + threadIdx.x;
    if (i >= n4) return;
    float4 v = src[i];
    __half2* d = reinterpret_cast<__half2*>(g_wh);
    d[2 * i]     = __floats2half2_rn(v.x, v.y);
    d[2 * i + 1] = __floats2half2_rn(v.z, v.w);
}

// ---------------- GEMM + partial logsumexp (per N-slice) ----------------
__global__ void __launch_bounds__(256, 2)
gemm_lse_part_kernel(const float* __restrict__ bias) {
    extern __shared__ char smem_raw[];
    const uint32_t sb0 = smem_u32(smem_raw);
    const uint32_t sb  = (sb0 + 1023u) & ~1023u;   // 1024-align
    char* sptr = smem_raw + (sb - sb0);

    const int tid  = threadIdx.x;
    const int wid  = tid >> 5;            // 0..7
    const int lane = tid & 31;
    const int mt   = blockIdx.x >> 4;     // m-tile (16 consecutive CTAs share A)
    const int ns   = blockIdx.x & 15;     // n-slice
    const int m0   = mt * BM;
    const int n0   = ns * BN;

    const int warpM = (wid >> 2) * 64;    // 0 or 64
    const int warpN = (wid & 3) * 64;     // 0,64,128,192 within BN

    // per-lane ldmatrix byte offsets (pre-swizzle)
    const int matid = lane >> 3, rin = lane & 7;
    int aRow[4], bRow[4];
    #pragma unroll
    for (int mi = 0; mi < 4; mi++)
        aRow[mi] = (warpM + mi * 16 + (matid & 1) * 8 + rin) * 128 + (matid >> 1) * 16;
    #pragma unroll
    for (int p = 0; p < 4; p++)
        bRow[p] = (warpN + p * 16 + (matid >> 1) * 8 + rin) * 128 + (matid & 1) * 16;

    // ---- producer addressing (uniform strides; 2 base ptrs + 1 smem off) ----
    // copy c = tid + 256*j : j<4 -> A row (tid>>3 + 32j), j>=4 -> B row (tid>>3 + 32(j-4))
    const int prow  = tid >> 3;
    const int pc16  = tid & 7;
    const char* srcA = (const char*)(g_xh + ((size_t)(m0 + prow) * K_DIM + pc16 * 8));
    const char* srcB = (const char*)(g_wh + ((size_t)(n0 + prow) * K_DIM + pc16 * 8));
    const uint32_t dstOff = swz((uint32_t)(prow * 128 + pc16 * 16));  // +4096/j commutes

    auto issue_stage = [&](int gs) {
        if (gs < TOTSTG) {
            const uint32_t offG = (uint32_t)gs << 8;   // gs * 128 B row-chunk * 2B? = gs*256? no:
            // gs-th K-slab: byte offset gs * BK * 2 = gs*128 bytes into each row
            const uint32_t offK = (uint32_t)gs << 7;
            const uint32_t base = sb + (uint32_t)(gs & 1) * STG;
            (void)offG;
            #pragma unroll
            for (int j = 0; j < 4; j++)
                cp_async16(base + dstOff + j * 4096,
                           srcA + offK + (size_t)j * (32 * K_DIM * 2));
            #pragma unroll
            for (int j = 0; j < 8; j++)
                cp_async16(base + A_STG + dstOff + j * 4096,
                           srcB + offK + (size_t)j * (32 * K_DIM * 2));
        }
        CP_COMMIT();
    };

    // fp16 accumulators: 4 m-tiles x 8 n-tiles x 2 regs
    uint32_t hacc[4][8][2];
    #pragma unroll
    for (int mi = 0; mi < 4; mi++)
        #pragma unroll
        for (int ni = 0; ni < 8; ni++) { hacc[mi][ni][0] = 0u; hacc[mi][ni][1] = 0u; }

    issue_stage(0); issue_stage(1);

    #pragma unroll 1
    for (int gs = 0; gs < TOTSTG; ++gs) {
        CP_WAIT(1);
        __syncthreads();                       // stage gs visible to all warps
        const uint32_t aB = sb + (uint32_t)(gs & 1) * STG;
        const uint32_t bB = aB + A_STG;
        #pragma unroll
        for (int g = 0; g < 4; g++) {
            uint32_t af[4][4], bt[4][4];
            #pragma unroll
            for (int mi = 0; mi < 4; mi++)
                ldsm4(af[mi], aB + swz((uint32_t)(aRow[mi] + g * 32)));
            #pragma unroll
            for (int p = 0; p < 4; p++)
                ldsm4(bt[p], bB + swz((uint32_t)(bRow[p] + g * 32)));
            #pragma unroll
            for (int mi = 0; mi < 4; mi++)
                #pragma unroll
                for (int p = 0; p < 4; p++) {
                    mma16816_h(hacc[mi][2 * p],     af[mi], &bt[p][0]);
                    mma16816_h(hacc[mi][2 * p + 1], af[mi], &bt[p][2]);
                }
        }
        __syncthreads();                       // all warps done with slot gs&1
        issue_stage(gs + 2);                   // refill the slot just freed
    }

    // fold logits (fp16 acc, K complete) into (max, sum)
    const int tg = lane & 3;
    float rm[8], rs[8];
    float bv[8][2];
    #pragma unroll
    for (int ni = 0; ni < 8; ni++) {
        const int nc = n0 + warpN + ni * 8 + tg * 2;
        bv[ni][0] = bias[nc];
        bv[ni][1] = bias[nc + 1];
    }
    #pragma unroll
    for (int mi = 0; mi < 4; mi++) {
        #pragma unroll
        for (int h = 0; h < 2; h++) {
            const int s = mi * 2 + h;
            float v[16], lm = -1e30f;
            #pragma unroll
            for (int ni = 0; ni < 8; ni++) {
                __half2 hv = *reinterpret_cast<__half2*>(&hacc[mi][ni][h]);
                float2 f = __half22float2(hv);
                v[ni * 2]     = f.x + bv[ni][0];
                v[ni * 2 + 1] = f.y + bv[ni][1];
                lm = fmaxf(lm, v[ni * 2]);
                lm = fmaxf(lm, v[ni * 2 + 1]);
            }
            float e = 0.f;
            #pragma unroll
            for (int j = 0; j < 16; j++) e += __expf(v[j] - lm);
            rm[s] = lm; rs[s] = e;
        }
    }

    // cross-thread reduction: quad shuffle, then across 4 N-warps via smem
    __syncthreads();
    float2* red = reinterpret_cast<float2*>(sptr);   // 128 rows x 4 warps
    #pragma unroll
    for (int s = 0; s < 8; s++) {
        float m = rm[s], sm = rs[s];
        #pragma unroll
        for (int d = 1; d <= 2; d <<= 1) {
            float om = __shfl_xor_sync(0xffffffffu, m, d);
            float os = __shfl_xor_sync(0xffffffffu, sm, d);
            float nm = fmaxf(m, om);
            sm = sm * __expf(m - nm) + os * __expf(om - nm);
            m = nm;
        }
        if (tg == 0) {
            const int mi = s >> 1, h = s & 1;
            const int row = warpM + mi * 16 + (lane >> 2) + h * 8;
            red[row * 4 + (wid & 3)] = make_float2(m, sm);
        }
    }
    __syncthreads();

    if (tid < BM) {
        float m = -1e30f, sm = 0.f;
        #pragma unroll
        for (int w = 0; w < 4; w++) {
            float2 p = red[tid * 4 + w];
            float nm = fmaxf(m, p.x);
            sm = sm * __expf(m - nm) + p.y * __expf(p.x - nm);
            m = nm;
        }
        g_part[(size_t)(m0 + tid) * 16 + ns] = make_float2(m, sm);
    }
}

// ---------------- combine partials + activations ----------------
__global__ void __launch_bounds__(256) combine_kernel(float* __restrict__ out) {
    const int i = blockIdx.x * 256 + threadIdx.x;
    if (i >= M_DIM) return;
    float m = -1e30f, sm = 0.f;
    #pragma unroll
    for (int ns = 0; ns < 16; ns++) {      // fixed order -> deterministic
        float2 p = g_part[(size_t)i * 16 + ns];
        float nm = fmaxf(m, p.x);
        sm = sm * __expf(m - nm) + p.y * __expf(p.x - nm);
        m = nm;
    }
    float v = m + logf(sm);
    v = v > 0.f ? v : 0.01f * v;           // LeakyReLU x2
    v = v > 0.f ? v : 0.01f * v;
    v = v * 0.5f * (1.0f + erff(v * 0.70710678118654752f));   // GELU x2
    v = v * 0.5f * (1.0f + erff(v * 0.70710678118654752f));
    out[i] = v;
}

extern "C" void kernel_launch(void* const* d_in, const int* in_sizes, int n_in,
                              void* d_out, int out_size) {
    const float* x = (const float*)d_in[0];
    const float* W = (const float*)d_in[1];
    const float* b = (const float*)d_in[2];
    float* out = (float*)d_out;

    cudaFuncSetAttribute(gemm_lse_part_kernel,
                         cudaFuncAttributeMaxDynamicSharedMemorySize, SMEM_BYTES);

    const int x4 = (M_DIM * K_DIM) / 4;
    const int w4 = (N_DIM * K_DIM) / 4;
    cvt_x_kernel<<<(x4 + 255) / 256, 256>>>((const float4*)x, x4);
    cvt_w_kernel<<<(w4 + 255) / 256, 256>>>((const float4*)W, w4);
    gemm_lse_part_kernel<<<(M_DIM / BM) * NSLICE, 256, SMEM_BYTES>>>(b);
    combine_kernel<<<(M_DIM + 255) / 256, 256>>>(out);
}

// round 12
// speedup vs baseline: 1.1330x; 1.0228x over previous
#include <cuda_runtime.h>
#include <cuda_fp16.h>
#include <cstdint>
#include <math.h>

#define M_DIM 16384
#define K_DIM 4096
#define N_DIM 4096

// fp16 copies of inputs + lse partials (static device scratch)
static __device__ __half g_xh[(size_t)M_DIM * K_DIM];
static __device__ __half g_wh[(size_t)N_DIM * K_DIM];
static __device__ float2 g_part[(size_t)M_DIM * 16];  // [row][nslice] (max,sum)

// ---------------- tile / smem geometry ----------------
constexpr int BM = 128;            // M tile per CTA
constexpr int BN = 256;            // N cols per CTA (single chunk)
constexpr int NSLICE = 16;         // N split across CTAs
constexpr int BK = 64;             // K halves per stage (128 B/row, SW128)
constexpr int NSTAGE = 2;
constexpr int TOTSTG = K_DIM / BK;           // 64 stages per CTA

constexpr uint32_t A_STG = BM * 128;         // 16 KB
constexpr uint32_t B_STG = BN * 128;         // 32 KB
constexpr uint32_t STG   = A_STG + B_STG;    // 48 KB
constexpr uint32_t SMEM_BYTES = NSTAGE * STG + 1024;   // 99328 -> 2 CTAs/SM

__device__ __forceinline__ uint32_t smem_u32(const void* p) {
    uint32_t a;
    asm("{ .reg .u64 t; cvta.to.shared.u64 t, %1; cvt.u32.u64 %0, t; }"
        : "=r"(a) : "l"(p));
    return a;
}
__device__ __forceinline__ uint32_t swz(uint32_t off) {   // SW128, 16B granule
    return off ^ ((off >> 3) & 0x70);
}
__device__ __forceinline__ uint32_t h2_bits(__half2 h) {
    return *reinterpret_cast<uint32_t*>(&h);
}
__device__ __forceinline__ void cp_async16(uint32_t dst, const void* src) {
    asm volatile("cp.async.cg.shared.global [%0], [%1], 16;"
                 :: "r"(dst), "l"(__cvta_generic_to_global(src)) : "memory");
}
#define CP_COMMIT() asm volatile("cp.async.commit_group;" ::: "memory")
#define CP_WAIT(n)  asm volatile("cp.async.wait_group %0;" :: "n"(n) : "memory")

__device__ __forceinline__ void ldsm4(uint32_t* r, uint32_t addr) {
    asm volatile("ldmatrix.sync.aligned.m8n8.x4.shared.b16 {%0,%1,%2,%3}, [%4];"
                 : "=r"(r[0]), "=r"(r[1]), "=r"(r[2]), "=r"(r[3]) : "r"(addr));
}
// fp16-accumulate MMA: D/C are 2 b32 regs (4 halves)
__device__ __forceinline__ void mma16816_h(uint32_t* c, const uint32_t* a, const uint32_t* b) {
    asm volatile(
        "mma.sync.aligned.m16n8k16.row.col.f16.f16.f16.f16 "
        "{%0,%1}, {%2,%3,%4,%5}, {%6,%7}, {%0,%1};"
        : "+r"(c[0]), "+r"(c[1])
        : "r"(a[0]), "r"(a[1]), "r"(a[2]), "r"(a[3]), "r"(b[0]), "r"(b[1]));
}

// ---------------- fp32 -> fp16 conversion (2x float4 -> 16B store) ----------------
__global__ void __launch_bounds__(256) cvt_x_kernel(const float4* __restrict__ src, int n8) {
    int i = blockIdx.x * 256 + threadIdx.x;
    if (i >= n8) return;
    float4 a = src[2 * i], b = src[2 * i + 1];
    uint4 o;
    o.x = h2_bits(__floats2half2_rn(a.x, a.y));
    o.y = h2_bits(__floats2half2_rn(a.z, a.w));
    o.z = h2_bits(__floats2half2_rn(b.x, b.y));
    o.w = h2_bits(__floats2half2_rn(b.z, b.w));
    reinterpret_cast<uint4*>(g_xh)[i] = o;
}
__global__ void __launch_bounds__(256) cvt_w_kernel(const float4* __restrict__ src, int n8) {
    int i = blockIdx.x * 256 + threadIdx.x;
    if (i >= n8) return;
    float4 a = src[2 * i], b = src[2 * i + 1];
    uint4 o;
    o.x = h2_bits(__floats2half2_rn(a.x, a.y));
    o.y = h2_bits(__floats2half2_rn(a.z, a.w));
    o.z = h2_bits(__floats2half2_rn(b.x, b.y));
    o.w = h2_bits(__floats2half2_rn(b.z, b.w));
    reinterpret_cast<uint4*>(g_wh)[i] = o;
}

// ---------------- GEMM + partial logsumexp (per N-slice) ----------------
__global__ void __launch_bounds__(256, 2)
gemm_lse_part_kernel(const float* __restrict__ bias) {
    extern __shared__ char smem_raw[];
    const uint32_t sb0 = smem_u32(smem_raw);
    const uint32_t sb  = (sb0 + 1023u) & ~1023u;   // 1024-align
    char* sptr = smem_raw + (sb - sb0);

    const int tid  = threadIdx.x;
    const int wid  = tid >> 5;            // 0..7
    const int lane = tid & 31;
    const int mt   = blockIdx.x >> 4;     // m-tile (16 consecutive CTAs share A)
    const int ns   = blockIdx.x & 15;     // n-slice
    const int m0   = mt * BM;
    const int n0   = ns * BN;

    const int warpM = (wid >> 2) * 64;    // 0 or 64
    const int warpN = (wid & 3) * 64;     // 0,64,128,192 within BN

    // per-lane ldmatrix byte offsets (pre-swizzle)
    const int matid = lane >> 3, rin = lane & 7;
    int aRow[4], bRow[4];
    #pragma unroll
    for (int mi = 0; mi < 4; mi++)
        aRow[mi] = (warpM + mi * 16 + (matid & 1) * 8 + rin) * 128 + (matid >> 1) * 16;
    #pragma unroll
    for (int p = 0; p < 4; p++)
        bRow[p] = (warpN + p * 16 + (matid >> 1) * 8 + rin) * 128 + (matid & 1) * 16;

    // ---- producer addressing (uniform strides) ----
    const int prow  = tid >> 3;
    const int pc16  = tid & 7;
    const char* srcA = (const char*)(g_xh + ((size_t)(m0 + prow) * K_DIM + pc16 * 8));
    const char* srcB = (const char*)(g_wh + ((size_t)(n0 + prow) * K_DIM + pc16 * 8));
    const uint32_t dstOff = swz((uint32_t)(prow * 128 + pc16 * 16));  // +4096/j commutes

    auto issue_stage = [&](int gs) {
        if (gs < TOTSTG) {
            const uint32_t offK = (uint32_t)gs << 7;   // gs * 128 B into each row
            const uint32_t base = sb + (uint32_t)(gs & 1) * STG;
            #pragma unroll
            for (int j = 0; j < 4; j++)
                cp_async16(base + dstOff + j * 4096,
                           srcA + offK + (size_t)j * (32 * K_DIM * 2));
            #pragma unroll
            for (int j = 0; j < 8; j++)
                cp_async16(base + A_STG + dstOff + j * 4096,
                           srcB + offK + (size_t)j * (32 * K_DIM * 2));
        }
        CP_COMMIT();
    };

    // fp16 accumulators: 4 m-tiles x 8 n-tiles x 2 regs
    uint32_t hacc[4][8][2];
    #pragma unroll
    for (int mi = 0; mi < 4; mi++)
        #pragma unroll
        for (int ni = 0; ni < 8; ni++) { hacc[mi][ni][0] = 0u; hacc[mi][ni][1] = 0u; }

    issue_stage(0);

    #pragma unroll 1
    for (int gs = 0; gs < TOTSTG; ++gs) {
        CP_WAIT(0);                            // stage gs complete (per-warp)
        __syncthreads();                       // visibility + all warps past gs-1
        issue_stage(gs + 1);                   // overwrites slot of gs-1 (safe)

        const uint32_t aB = sb + (uint32_t)(gs & 1) * STG;
        const uint32_t bB = aB + A_STG;
        #pragma unroll
        for (int g = 0; g < 4; g++) {
            uint32_t af[4][4], bt[4][4];
            #pragma unroll
            for (int mi = 0; mi < 4; mi++)
                ldsm4(af[mi], aB + swz((uint32_t)(aRow[mi] + g * 32)));
            #pragma unroll
            for (int p = 0; p < 4; p++)
                ldsm4(bt[p], bB + swz((uint32_t)(bRow[p] + g * 32)));
            #pragma unroll
            for (int mi = 0; mi < 4; mi++)
                #pragma unroll
                for (int p = 0; p < 4; p++) {
                    mma16816_h(hacc[mi][2 * p],     af[mi], &bt[p][0]);
                    mma16816_h(hacc[mi][2 * p + 1], af[mi], &bt[p][2]);
                }
        }
    }

    // fold logits (fp16 acc, K complete) into (max, sum)
    const int tg = lane & 3;
    float rm[8], rs[8];
    float bv[8][2];
    #pragma unroll
    for (int ni = 0; ni < 8; ni++) {
        const int nc = n0 + warpN + ni * 8 + tg * 2;
        bv[ni][0] = bias[nc];
        bv[ni][1] = bias[nc + 1];
    }
    #pragma unroll
    for (int mi = 0; mi < 4; mi++) {
        #pragma unroll
        for (int h = 0; h < 2; h++) {
            const int s = mi * 2 + h;
            float v[16], lm = -1e30f;
            #pragma unroll
            for (int ni = 0; ni < 8; ni++) {
                __half2 hv = *reinterpret_cast<__half2*>(&hacc[mi][ni][h]);
                float2 f = __half22float2(hv);
                v[ni * 2]     = f.x + bv[ni][0];
                v[ni * 2 + 1] = f.y + bv[ni][1];
                lm = fmaxf(lm, v[ni * 2]);
                lm = fmaxf(lm, v[ni * 2 + 1]);
            }
            float e = 0.f;
            #pragma unroll
            for (int j = 0; j < 16; j++) e += __expf(v[j] - lm);
            rm[s] = lm; rs[s] = e;
        }
    }

    // cross-thread reduction: quad shuffle, then across 4 N-warps via smem
    __syncthreads();
    float2* red = reinterpret_cast<float2*>(sptr);   // 128 rows x 4 warps
    #pragma unroll
    for (int s = 0; s < 8; s++) {
        float m = rm[s], sm = rs[s];
        #pragma unroll
        for (int d = 1; d <= 2; d <<= 1) {
            float om = __shfl_xor_sync(0xffffffffu, m, d);
            float os = __shfl_xor_sync(0xffffffffu, sm, d);
            float nm = fmaxf(m, om);
            sm = sm * __expf(m - nm) + os * __expf(om - nm);
            m = nm;
        }
        if (tg == 0) {
            const int mi = s >> 1, h = s & 1;
            const int row = warpM + mi * 16 + (lane >> 2) + h * 8;
            red[row * 4 + (wid & 3)] = make_float2(m, sm);
        }
    }
    __syncthreads();

    if (tid < BM) {
        float m = -1e30f, sm = 0.f;
        #pragma unroll
        for (int w = 0; w < 4; w++) {
            float2 p = red[tid * 4 + w];
            float nm = fmaxf(m, p.x);
            sm = sm * __expf(m - nm) + p.y * __expf(p.x - nm);
            m = nm;
        }
        g_part[(size_t)(m0 + tid) * 16 + ns] = make_float2(m, sm);
    }
}

// ---------------- combine partials + activations ----------------
__global__ void __launch_bounds__(256) combine_kernel(float* __restrict__ out) {
    const int i = blockIdx.x * 256 + threadIdx.x;
    if (i >= M_DIM) return;
    float m = -1e30f, sm = 0.f;
    #pragma unroll
    for (int ns = 0; ns < 16; ns++) {      // fixed order -> deterministic
        float2 p = g_part[(size_t)i * 16 + ns];
        float nm = fmaxf(m, p.x);
        sm = sm * __expf(m - nm) + p.y * __expf(p.x - nm);
        m = nm;
    }
    float v = m + logf(sm);
    v = v > 0.f ? v : 0.01f * v;           // LeakyReLU x2
    v = v > 0.f ? v : 0.01f * v;
    v = v * 0.5f * (1.0f + erff(v * 0.70710678118654752f));   // GELU x2
    v = v * 0.5f * (1.0f + erff(v * 0.70710678118654752f));
    out[i] = v;
}

extern "C" void kernel_launch(void* const* d_in, const int* in_sizes, int n_in,
                              void* d_out, int out_size) {
    const float* x = (const float*)d_in[0];
    const float* W = (const float*)d_in[1];
    const float* b = (const float*)d_in[2];
    float* out = (float*)d_out;

    cudaFuncSetAttribute(gemm_lse_part_kernel,
                         cudaFuncAttributeMaxDynamicSharedMemorySize, SMEM_BYTES);

    const int x8 = (M_DIM * K_DIM) / 8;
    const int w8 = (N_DIM * K_DIM) / 8;
    cvt_x_kernel<<<(x8 + 255) / 256, 256>>>((const float4*)x, x8);
    cvt_w_kernel<<<(w8 + 255) / 256, 256>>>((const float4*)W, w8);
    gemm_lse_part_kernel<<<(M_DIM / BM) * NSLICE, 256, SMEM_BYTES>>>(b);
    combine_kernel<<<(M_DIM + 255) / 256, 256>>>(out);
}